// round 16
// baseline (speedup 1.0000x reference)
#include <cuda_runtime.h>
#include <cuda_fp16.h>
#include <cstdint>

#define NUM_EXPERT 16
#define IN_FEAT 1024
#define OUT_FEAT 1024
#define BATCH 8192

#define BM 128
#define BN 128
#define NKSTEP 64                 // 1024 k / 16 per mma
#define THREADS 128               // 4 warps, 64x64 warp tile
#define MAX_TILES 79

#define WBLOCKS (NUM_EXPERT * OUT_FEAT * IN_FEAT / 2 / 4 / 256)  // 8192
#define SBLOCKS (BATCH / 256)                                    // 32
#define AFBLOCKS (MAX_TILES * 64)                                // 5056: 16384 thr/tile

__device__ int g_counts[NUM_EXPERT];
__device__ int g_rows[NUM_EXPERT * BATCH];
// W in HMMA B-fragment layout: [e][ntile(32)][half32k(32)][j(4)][lane(32)] uint4
__device__ uint4 g_wf[NUM_EXPERT * 32 * 32 * 128];               // 33.5 MB
// A in HMMA A-fragment layout: [ty][mhalf(2)][kstep(64)][mt(4)][lane(32)] uint4
__device__ uint4 g_af[MAX_TILES * 2 * 64 * 4 * 32];              // 20.2 MB

// ---------------- helpers ----------------
__device__ __forceinline__ uint32_t pack_h2(float x, float y) {
    uint32_t r;
    asm("cvt.rn.f16x2.f32 %0, %1, %2;" : "=r"(r) : "f"(y), "f"(x));
    return r;
}
__device__ __forceinline__ void mma16816(float* d, const uint32_t* a, const uint32_t* b) {
    asm volatile(
        "mma.sync.aligned.m16n8k16.row.col.f32.f16.f16.f32 "
        "{%0,%1,%2,%3}, {%4,%5,%6,%7}, {%8,%9}, {%0,%1,%2,%3};"
        : "+f"(d[0]), "+f"(d[1]), "+f"(d[2]), "+f"(d[3])
        : "r"(a[0]), "r"(a[1]), "r"(a[2]), "r"(a[3]), "r"(b[0]), "r"(b[1]));
}
// map tile index ty -> (expert, tile-in-expert, count); e=-1 if out of range
__device__ __forceinline__ void tile_map(int ty, int& e, int& tt, int& cnt) {
    e = -1; tt = 0; cnt = 0;
    int n = 0;
    #pragma unroll
    for (int i = 0; i < NUM_EXPERT; i++) {
        int ci = g_counts[i];
        int nti = (ci + BM - 1) >> 7;
        if (e < 0 && ty < n + nti) { e = i; tt = ty - n; cnt = ci; }
        n += nti;
    }
}

// ---------------- kernel 1: routing scatter + W fragment permute ----------------
__global__ __launch_bounds__(256)
void prep_w_kernel(const float* __restrict__ w, const int* __restrict__ gate) {
    if (blockIdx.x < WBLOCKS) {
        int t = blockIdx.x * 256 + threadIdx.x;
        int l = t & 31, j = (t >> 5) & 3, c = (t >> 7) & 31;
        int nt = (t >> 12) & 31, e = t >> 17;
        int ks = j >> 1;
        int kbase = c * 32 + ks * 16 + (l & 3) * 2;
        uint4 d;
        uint32_t* dq = (uint32_t*)&d;
        #pragma unroll
        for (int q = 0; q < 4; q++) {
            int n = nt * 32 + ((j & 1) * 2 + (q >> 1)) * 8 + (l >> 2);
            int k = kbase + (q & 1) * 8;
            float2 v = *reinterpret_cast<const float2*>(
                w + (((size_t)e << 10) + n) * IN_FEAT + k);
            dq[q] = pack_h2(v.x, v.y);
        }
        g_wf[t] = d;
    } else {
        int jj = (blockIdx.x - WBLOCKS) * 256 + threadIdx.x;
        if (jj < BATCH) {
            int e = gate[jj];
            int pos = atomicAdd(&g_counts[e], 1);
            g_rows[e * BATCH + pos] = jj;
        }
    }
}

// ---------------- kernel 2: A gather + convert + fragment permute ----------------
// Output uint4 = {a0=(r1,k0), a1=(r2,k0), a2=(r1,k0+8), a3=(r2,k0+8)}, r2 = r1+8
__global__ __launch_bounds__(256)
void prep_a_kernel(const float* __restrict__ inp) {
    int t = blockIdx.x * 256 + threadIdx.x;
    int lane = t & 31, mt = (t >> 5) & 3, s = (t >> 7) & 63;
    int mhalf = (t >> 13) & 1, ty = t >> 14;

    int e, tt, cnt;
    tile_map(ty, e, tt, cnt);
    if (e < 0) return;
    const int row0 = tt * BM;

    int ridx = mhalf * 64 + mt * 16 + (lane >> 2);
    int k0 = s * 16 + (lane & 3) * 2;
    int i1 = row0 + ridx;
    int i2 = i1 + 8;
    int g1 = (i1 < cnt) ? g_rows[e * BATCH + i1] : -1;
    int g2 = (i2 < cnt) ? g_rows[e * BATCH + i2] : -1;

    uint4 d = make_uint4(0u, 0u, 0u, 0u);
    if (g1 >= 0) {
        float2 v0 = *reinterpret_cast<const float2*>(inp + ((size_t)g1 << 10) + k0);
        float2 v1 = *reinterpret_cast<const float2*>(inp + ((size_t)g1 << 10) + k0 + 8);
        d.x = pack_h2(v0.x, v0.y);
        d.z = pack_h2(v1.x, v1.y);
    }
    if (g2 >= 0) {
        float2 v0 = *reinterpret_cast<const float2*>(inp + ((size_t)g2 << 10) + k0);
        float2 v1 = *reinterpret_cast<const float2*>(inp + ((size_t)g2 << 10) + k0 + 8);
        d.y = pack_h2(v0.x, v0.y);
        d.w = pack_h2(v1.x, v1.y);
    }
    g_af[t] = d;
}

// ---------------- grouped GEMM: all-fragment LDG, no smem, no barriers ----------------
__global__ __launch_bounds__(THREADS, 2)
void moe_mma_kernel(float* __restrict__ out) {
    const int ty = blockIdx.y;
    int e, tt, cnt;
    tile_map(ty, e, tt, cnt);
    if (e < 0) return;
    const int row0 = tt * BM;
    const int nx = blockIdx.x;

    const int tid = threadIdx.x;
    const int wid = tid >> 5;
    const int lane = tid & 31;
    const int warp_m = wid >> 1;      // 0..1 -> 64-row half
    const int warp_n = wid & 1;       // 0..1 -> 64-col half

    // A fragments: per kstep s, mt: ap + s*128 + mt*32
    const uint4* ap = g_af + (((size_t)(ty * 2 + warp_m)) << 13) + lane;
    // W fragments: ntile0 = nx*4 + warp_n*2; per kstep s: h=s>>1, j=(s&1)*2+jj
    const uint4* wp = g_wf + ((size_t)((e * 32 + nx * 4 + warp_n * 2) * 32)) * 128 + lane;

    float acc[4][8][4];
    #pragma unroll
    for (int mt = 0; mt < 4; mt++)
        #pragma unroll
        for (int nt = 0; nt < 8; nt++)
            #pragma unroll
            for (int q = 0; q < 4; q++) acc[mt][nt][q] = 0.0f;

    uint32_t ab[2][16], wb[2][16];

    // load kstep 0 into buffer 0
    #pragma unroll
    for (int mt = 0; mt < 4; mt++) {
        uint4 t = __ldg(ap + mt * 32);
        ab[0][mt * 4 + 0] = t.x; ab[0][mt * 4 + 1] = t.y;
        ab[0][mt * 4 + 2] = t.z; ab[0][mt * 4 + 3] = t.w;
    }
    #pragma unroll
    for (int u = 0; u < 4; u++) {   // u = tsel*2 + jj
        uint4 t = __ldg(wp + (u >> 1) * 4096 + (u & 1) * 32);
        wb[0][u * 4 + 0] = t.x; wb[0][u * 4 + 1] = t.y;
        wb[0][u * 4 + 2] = t.z; wb[0][u * 4 + 3] = t.w;
    }

    #pragma unroll 2
    for (int s = 0; s < NKSTEP; s++) {
        const int b = s & 1;
        // prefetch kstep s+1 into the other buffer
        if (s + 1 < NKSTEP) {
            const int sn = s + 1;
            const int nb = b ^ 1;
            #pragma unroll
            for (int mt = 0; mt < 4; mt++) {
                uint4 t = __ldg(ap + sn * 128 + mt * 32);
                wb[0][0] = wb[0][0];  // no-op to keep formatting honest
                ab[nb][mt * 4 + 0] = t.x; ab[nb][mt * 4 + 1] = t.y;
                ab[nb][mt * 4 + 2] = t.z; ab[nb][mt * 4 + 3] = t.w;
            }
            const int h = sn >> 1;
            const int jb = (sn & 1) * 2;
            #pragma unroll
            for (int u = 0; u < 4; u++) {
                uint4 t = __ldg(wp + (u >> 1) * 4096 + h * 128 + (jb + (u & 1)) * 32);
                wb[nb][u * 4 + 0] = t.x; wb[nb][u * 4 + 1] = t.y;
                wb[nb][u * 4 + 2] = t.z; wb[nb][u * 4 + 3] = t.w;
            }
        }
        // compute kstep s
        #pragma unroll
        for (int mt = 0; mt < 4; mt++)
            #pragma unroll
            for (int nt = 0; nt < 8; nt++) {
                const int u = (nt >> 2) * 2 + ((nt & 3) >> 1);
                const int pair = (nt & 1) * 2;
                mma16816(acc[mt][nt], &ab[b][mt * 4], &wb[b][u * 4 + pair]);
            }
    }

    // ---- epilogue: scatter accumulators to out (row mapping via g_rows)
    #pragma unroll
    for (int mt = 0; mt < 4; mt++) {
        int i1 = row0 + warp_m * 64 + mt * 16 + (lane >> 2);
        int i2 = i1 + 8;
        int r0 = (i1 < cnt) ? g_rows[e * BATCH + i1] : -1;
        int r1 = (i2 < cnt) ? g_rows[e * BATCH + i2] : -1;
        #pragma unroll
        for (int nt = 0; nt < 8; nt++) {
            int col = nx * BN + warp_n * 64 + nt * 8 + (lane & 3) * 2;
            if (r0 >= 0)
                *reinterpret_cast<float2*>(out + ((size_t)r0 << 10) + col) =
                    make_float2(acc[mt][nt][0], acc[mt][nt][1]);
            if (r1 >= 0)
                *reinterpret_cast<float2*>(out + ((size_t)r1 << 10) + col) =
                    make_float2(acc[mt][nt][2], acc[mt][nt][3]);
        }
    }
}

extern "C" void kernel_launch(void* const* d_in, const int* in_sizes, int n_in,
                              void* d_out, int out_size) {
    const float* inp    = (const float*)d_in[0];   // [8192, 1024] f32
    const int*   gate   = (const int*)d_in[1];     // [8192] i32
    const float* weight = (const float*)d_in[2];   // [16, 1024, 1024] f32
    float* out = (float*)d_out;                    // [8192, 1024] f32

    void* counts_ptr = nullptr;
    cudaGetSymbolAddress(&counts_ptr, g_counts);
    cudaMemsetAsync(counts_ptr, 0, NUM_EXPERT * sizeof(int));

    prep_w_kernel<<<WBLOCKS + SBLOCKS, 256>>>(weight, gate);
    prep_a_kernel<<<AFBLOCKS, 256>>>(inp);

    dim3 grid(OUT_FEAT / BN, MAX_TILES, 1);
    moe_mma_kernel<<<grid, THREADS>>>(out);
}